// round 5
// baseline (speedup 1.0000x reference)
#include <cuda_runtime.h>
#include <math.h>

#define Bn   8
#define Sn   8192
#define Dn   384
#define CHn  64
#define NCn  128
#define OUT_ELEMS  (Bn*Sn*Dn)     // 25165824
#define MFIN_ELEMS (Bn*Dn*Dn)     // 1179648

// ---------------- static scratch (no allocations) ----------------
// g_V rows: v in [0,128) = w_t (x_mean - k_mean); v in [128,256) = k_t (k_mean)
__device__ float g_V [Bn*256*Dn];
__device__ float g_WW[Bn*256*Dn];   // v<128: M0@w_t ; v>=128: M0@k_t
__device__ float g_GG[Bn*256*NCn];  // v<128: w_t.k_j ; v>=128: k_t.k_j
__device__ float g_P [Bn*Sn*NCn];   // X[b,s].k_j
__device__ float g_E [Bn*NCn*Dn];   // err vectors
__device__ float g_r [Bn*NCn];      // r_j = B_j/Q_j
__device__ float g_Qp[Bn*NCn];      // Q_{t-1}
__device__ float g_gd[Bn*NCn];      // k_t . gate_w
__device__ float g_dc[Bn*NCn];      // Q_N * r_j
__device__ float g_QN[Bn];

// ---------------- P1: per-chunk means + row-normalized key means ----------------
__global__ void __launch_bounds__(384) p1_kernel(const float* __restrict__ x,
                                                 const float* __restrict__ gw) {
    extern __shared__ float Xs[];            // 64*384 floats
    __shared__ float inv[CHn];
    __shared__ float red[12];
    int t = blockIdx.x, b = blockIdx.y, tid = threadIdx.x;
    int w = tid >> 5, l = tid & 31;
    const float* src = x + ((long)(b*Sn) + (long)t*CHn)*Dn;
    for (int i = tid; i < CHn*Dn; i += 384) Xs[i] = src[i];
    __syncthreads();
    for (int r = w; r < CHn; r += 12) {
        float s = 0.f;
        for (int d = l; d < Dn; d += 32) { float v = Xs[r*Dn+d]; s += v*v; }
        #pragma unroll
        for (int o = 16; o > 0; o >>= 1) s += __shfl_down_sync(0xffffffffu, s, o);
        if (l == 0) inv[r] = 1.0f / fmaxf(sqrtf(s), 1e-5f);
    }
    __syncthreads();
    float sx = 0.f, sk = 0.f;
    for (int c = 0; c < CHn; c++) {
        float v = Xs[c*Dn + tid];
        sx += v; sk += v * inv[c];
    }
    float km = sk * (1.0f/CHn);
    float wm = sx * (1.0f/CHn) - km;
    g_V[((long)b*256 + t)*Dn + tid]       = wm;
    g_V[((long)b*256 + 128 + t)*Dn + tid] = km;
    float gd = km * gw[tid];
    #pragma unroll
    for (int o = 16; o > 0; o >>= 1) gd += __shfl_down_sync(0xffffffffu, gd, o);
    if (l == 0) red[w] = gd;
    __syncthreads();
    if (tid == 0) {
        float s = 0.f;
        #pragma unroll
        for (int i = 0; i < 12; i++) s += red[i];
        g_gd[b*NCn + t] = s;
    }
}

// ---------------- generic 64x64 tile GEMM: C = A * B^T (A:[M,K], B:[N,K] row-major) ----------------
__device__ __forceinline__ void gemm_tile64(const float* __restrict__ A,
                                            const float* __restrict__ B,
                                            float* __restrict__ C,
                                            int K, int N) {
    __shared__ float As[64][33];
    __shared__ float Bs[32][65];
    int row0 = blockIdx.y * 64, col0 = blockIdx.x * 64;
    int tid = threadIdx.x, tx = tid & 15, ty = tid >> 4;
    int kk = tid & 31, rr = tid >> 5;
    float acc[4][4] = {};
    for (int k0 = 0; k0 < K; k0 += 32) {
        #pragma unroll
        for (int r = rr; r < 64; r += 8) As[r][kk] = A[(long)(row0 + r)*K + k0 + kk];
        #pragma unroll
        for (int c = rr; c < 64; c += 8) Bs[kk][c] = B[(long)(col0 + c)*K + k0 + kk];
        __syncthreads();
        #pragma unroll
        for (int k = 0; k < 32; k++) {
            float av[4], bv[4];
            #pragma unroll
            for (int i = 0; i < 4; i++) av[i] = As[ty*4+i][k];
            #pragma unroll
            for (int j = 0; j < 4; j++) bv[j] = Bs[k][tx*4+j];
            #pragma unroll
            for (int i = 0; i < 4; i++)
                #pragma unroll
                for (int j = 0; j < 4; j++)
                    acc[i][j] = fmaf(av[i], bv[j], acc[i][j]);
        }
        __syncthreads();
    }
    #pragma unroll
    for (int i = 0; i < 4; i++)
        #pragma unroll
        for (int j = 0; j < 4; j++)
            C[(long)(row0 + ty*4 + i)*N + col0 + tx*4 + j] = acc[i][j];
}

__global__ void __launch_bounds__(256) p2a_kernel(const float* __restrict__ M0) {
    int b = blockIdx.z;
    gemm_tile64(g_V + (long)b*256*Dn, M0, g_WW + (long)b*256*Dn, Dn, Dn);
}
__global__ void __launch_bounds__(256) p2b_kernel() {
    int b = blockIdx.z;
    gemm_tile64(g_V + (long)b*256*Dn, g_V + (long)b*256*Dn + 128*Dn,
                g_GG + (long)b*256*NCn, Dn, NCn);
}
__global__ void __launch_bounds__(256) p2c_kernel(const float* __restrict__ x) {
    int b = blockIdx.z;
    gemm_tile64(x + (long)b*Sn*Dn, g_V + (long)b*256*Dn + 128*Dn,
                g_P + (long)b*Sn*NCn, Dn, NCn);
}

// ---------------- P3: sequential scalar/vector recurrence, one CTA per batch ----------------
__global__ void __launch_bounds__(384) p3_kernel(const float* __restrict__ M0,
                                                 const float* __restrict__ gb,
                                                 const float* __restrict__ eta_raw,
                                                 const float* __restrict__ alpha_raw) {
    extern __shared__ float Es[];            // 128*384 floats = 192 KB
    __shared__ float2 cgh[NCn];
    __shared__ float rs[NCn];
    __shared__ float redA[12], redB[12];
    __shared__ float sQ;
    int b = blockIdx.x, tid = threadIdx.x;
    int w = tid >> 5, l = tid & 31;

    float eta   = 0.2f / (1.0f + expf(-eta_raw[0]));
    float alpha = 0.5f + 0.5f / (1.0f + expf(-alpha_raw[0]));
    float gbv   = gb[0];

    // ||M0||_F^2
    float s0 = 0.f;
    for (int i = tid; i < Dn*Dn; i += 384) { float v = M0[i]; s0 += v*v; }
    #pragma unroll
    for (int o = 16; o > 0; o >>= 1) s0 += __shfl_down_sync(0xffffffffu, s0, o);
    if (l == 0) redA[w] = s0;
    if (tid == 0) sQ = 1.0f;
    __syncthreads();
    float n2 = 0.f, Qr = 1.0f;               // thread-0 state
    if (tid == 0) { for (int i = 0; i < 12; i++) n2 += redA[i]; }

    const float* WWb = g_WW + (long)b*256*Dn;
    const float* GGb = g_GG + (long)b*256*NCn;

    for (int t = 0; t < NCn; t++) {
        if (tid < t) {
            float r = rs[tid];
            cgh[tid] = make_float2(r * GGb[t*NCn + tid], r * GGb[(128+t)*NCn + tid]);
        }
        __syncthreads();                                   // (a)
        float acc_e = WWb[t*Dn + tid];
        float acc_m = WWb[(128+t)*Dn + tid];
        for (int j = 0; j < t; j++) {
            float e = Es[j*Dn + tid];
            float2 c = cgh[j];
            acc_e = fmaf(c.x, e, acc_e);
            acc_m = fmaf(c.y, e, acc_m);
        }
        float Q   = sQ;
        float err = Q * acc_e;
        float mk  = Q * acc_m;
        Es[t*Dn + tid] = err;
        g_E[((long)b*NCn + t)*Dn + tid] = err;
        float ee = err*err, em = err*mk;
        #pragma unroll
        for (int o = 16; o > 0; o >>= 1) {
            ee += __shfl_down_sync(0xffffffffu, ee, o);
            em += __shfl_down_sync(0xffffffffu, em, o);
        }
        if (l == 0) { redA[w] = ee; redB[w] = em; }
        __syncthreads();                                   // (b)
        if (tid == 0) {
            float see = 0.f, sem = 0.f;
            #pragma unroll
            for (int i = 0; i < 12; i++) { see += redA[i]; sem += redB[i]; }
            float kk2  = GGb[(128+t)*NCn + t];             // ||k_t||^2
            float gate = 1.0f / (1.0f + expf(-(g_gd[b*NCn + t] + gbv)));
            float a  = gate*alpha + (1.0f - gate);
            float bb = gate*eta;
            float norm2 = a*a*n2 + 2.0f*a*bb*sem + bb*bb*see*kk2;
            float s = fminf(30.0f / (sqrtf(norm2) + 1e-6f), 1.0f);
            g_Qp[b*NCn + t] = Qr;
            float A = s*a, Bc = s*bb;
            float Qn = Qr*A;
            float rt = Bc / Qn;
            rs[t] = rt;
            g_r[b*NCn + t] = rt;
            n2 = s*s*norm2;
            Qr = Qn;
            sQ = Qn;
        }
        __syncthreads();                                   // (c)
    }
    if (tid < NCn) g_dc[b*NCn + tid] = sQ * rs[tid];
    if (tid == 0)  g_QN[b] = sQ;
}

// ---------------- P4: fused output GEMM: out = Q_{t-1}*(X@M0^T + P_masked @ diag(r) E) ----------------
__global__ void __launch_bounds__(256) p4_kernel(const float* __restrict__ x,
                                                 const float* __restrict__ M0,
                                                 float* __restrict__ out) {
    __shared__ float As[64][33];
    __shared__ float Bs[32][65];
    __shared__ float rc[NCn];
    int ot = blockIdx.x, t = blockIdx.y, b = blockIdx.z;
    int tid = threadIdx.x, tx = tid & 15, ty = tid >> 4;
    int kk = tid & 31, rr = tid >> 5;
    int col0 = ot * 64;
    const float* Xc = x   + ((long)b*Sn + (long)t*CHn)*Dn;
    const float* Pc = g_P + ((long)b*Sn + (long)t*CHn)*NCn;
    float acc[4][4] = {};
    // phase 1: X @ M0^T, K = 384
    for (int k0 = 0; k0 < Dn; k0 += 32) {
        #pragma unroll
        for (int r = rr; r < 64; r += 8) As[r][kk] = Xc[(long)r*Dn + k0 + kk];
        #pragma unroll
        for (int c = rr; c < 64; c += 8) Bs[kk][c] = M0[(long)(col0 + c)*Dn + k0 + kk];
        __syncthreads();
        #pragma unroll
        for (int k = 0; k < 32; k++) {
            float av[4], bv[4];
            #pragma unroll
            for (int i = 0; i < 4; i++) av[i] = As[ty*4+i][k];
            #pragma unroll
            for (int j = 0; j < 4; j++) bv[j] = Bs[k][tx*4+j];
            #pragma unroll
            for (int i = 0; i < 4; i++)
                #pragma unroll
                for (int j = 0; j < 4; j++)
                    acc[i][j] = fmaf(av[i], bv[j], acc[i][j]);
        }
        __syncthreads();
    }
    // phase 2: P(:, j<t) @ diag(r) E, K = t rounded up
    if (tid < NCn) rc[tid] = (tid < t) ? g_r[b*NCn + tid] : 0.0f;
    __syncthreads();
    int Kt = (t + 31) & ~31;
    for (int k0 = 0; k0 < Kt; k0 += 32) {
        #pragma unroll
        for (int r = rr; r < 64; r += 8) As[r][kk] = Pc[(long)r*NCn + k0 + kk];
        for (int k = rr; k < 32; k += 8) {
            float rj = rc[k0 + k];
            #pragma unroll
            for (int c = kk; c < 64; c += 32)
                Bs[k][c] = g_E[((long)b*NCn + k0 + k)*Dn + col0 + c] * rj;
        }
        __syncthreads();
        #pragma unroll
        for (int k = 0; k < 32; k++) {
            float av[4], bv[4];
            #pragma unroll
            for (int i = 0; i < 4; i++) av[i] = As[ty*4+i][k];
            #pragma unroll
            for (int j = 0; j < 4; j++) bv[j] = Bs[k][tx*4+j];
            #pragma unroll
            for (int i = 0; i < 4; i++)
                #pragma unroll
                for (int j = 0; j < 4; j++)
                    acc[i][j] = fmaf(av[i], bv[j], acc[i][j]);
        }
        __syncthreads();
    }
    float Qp = g_Qp[b*NCn + t];
    float* O = out + ((long)b*Sn + (long)t*CHn)*Dn;
    #pragma unroll
    for (int i = 0; i < 4; i++)
        #pragma unroll
        for (int j = 0; j < 4; j++)
            O[(long)(ty*4 + i)*Dn + col0 + tx*4 + j] = Qp * acc[i][j];
}

// ---------------- P5: M_fin = Q_N*M0 + E^T diag(Q_N r) K ----------------
__global__ void __launch_bounds__(256) p5_kernel(const float* __restrict__ M0,
                                                 float* __restrict__ out2) {
    __shared__ float As[32][65];
    __shared__ float Bs[32][65];
    int b = blockIdx.z;
    int row0 = blockIdx.y * 64, col0 = blockIdx.x * 64;
    int tid = threadIdx.x, tx = tid & 15, ty = tid >> 4;
    int kk = tid & 31, rr = tid >> 5;
    float acc[4][4] = {};
    for (int k0 = 0; k0 < NCn; k0 += 32) {
        for (int k = rr; k < 32; k += 8) {
            float dc = g_dc[b*NCn + k0 + k];
            #pragma unroll
            for (int c = kk; c < 64; c += 32) {
                As[k][c] = g_E[((long)b*NCn + k0 + k)*Dn + row0 + c] * dc;
                Bs[k][c] = g_V[((long)b*256 + 128 + k0 + k)*Dn + col0 + c];
            }
        }
        __syncthreads();
        #pragma unroll
        for (int k = 0; k < 32; k++) {
            float av[4], bv[4];
            #pragma unroll
            for (int i = 0; i < 4; i++) av[i] = As[k][ty*4+i];
            #pragma unroll
            for (int j = 0; j < 4; j++) bv[j] = Bs[k][tx*4+j];
            #pragma unroll
            for (int i = 0; i < 4; i++)
                #pragma unroll
                for (int j = 0; j < 4; j++)
                    acc[i][j] = fmaf(av[i], bv[j], acc[i][j]);
        }
        __syncthreads();
    }
    float qn = g_QN[b];
    #pragma unroll
    for (int i = 0; i < 4; i++)
        #pragma unroll
        for (int j = 0; j < 4; j++) {
            int o = row0 + ty*4 + i, d = col0 + tx*4 + j;
            out2[((long)b*Dn + o)*Dn + d] = qn * M0[(long)o*Dn + d] + acc[i][j];
        }
}

extern "C" void kernel_launch(void* const* d_in, const int* in_sizes, int n_in,
                              void* d_out, int out_size) {
    const float* x         = (const float*)d_in[0];
    const float* M0        = (const float*)d_in[1];
    const float* eta_raw   = (const float*)d_in[2];
    const float* alpha_raw = (const float*)d_in[3];
    const float* gw        = (const float*)d_in[4];
    const float* gb        = (const float*)d_in[5];
    float* out = (float*)d_out;

    cudaFuncSetAttribute(p1_kernel, cudaFuncAttributeMaxDynamicSharedMemorySize, CHn*Dn*4);
    cudaFuncSetAttribute(p3_kernel, cudaFuncAttributeMaxDynamicSharedMemorySize, NCn*Dn*4);

    p1_kernel<<<dim3(NCn, Bn), 384, CHn*Dn*4>>>(x, gw);
    p2a_kernel<<<dim3(Dn/64, 256/64, Bn), 256>>>(M0);
    p2b_kernel<<<dim3(NCn/64, 256/64, Bn), 256>>>();
    p2c_kernel<<<dim3(NCn/64, Sn/64, Bn), 256>>>(x);
    p3_kernel<<<Bn, 384, NCn*Dn*4>>>(M0, gb, eta_raw, alpha_raw);
    p4_kernel<<<dim3(Dn/64, NCn, Bn), 256>>>(x, M0, out);
    if (out_size >= OUT_ELEMS + MFIN_ELEMS)
        p5_kernel<<<dim3(Dn/64, Dn/64, Bn), 256>>>(M0, out + OUT_ELEMS);
}

// round 7
// speedup vs baseline: 1.3243x; 1.3243x over previous
#include <cuda_runtime.h>
#include <cuda_bf16.h>
#include <math.h>

#define Bn   8
#define Sn   8192
#define Dn   384
#define CHn  64
#define NCn  128
#define OUT_ELEMS  (Bn*Sn*Dn)     // 25165824
#define MFIN_ELEMS (Bn*Dn*Dn)     // 1179648

// ---------------- static scratch (no allocations) ----------------
__device__ float g_V [Bn*256*Dn];   // v<128: w_t = x_mean - k_mean ; v>=128: k_t
__device__ float g_WW[Bn*256*Dn];   // v<128: M0@w_t ; v>=128: M0@k_t
__device__ float g_GG[Bn*256*NCn];  // v<128: w_t.k_j ; v>=128: k_t.k_j
__device__ float g_P [Bn*Sn*NCn];   // X[b,s].k_j
__device__ float g_E [Bn*NCn*Dn];   // err vectors
__device__ float g_r [Bn*NCn];      // r_j = B_j/Q_j
__device__ float g_Qp[Bn*NCn];      // Q_{t-1}
__device__ float g_gd[Bn*NCn];      // k_t . gate_w
__device__ float g_dc[Bn*NCn];      // Q_N * r_j
__device__ float g_QN[Bn];

// ================= mma.sync helpers =================
__device__ __forceinline__ unsigned smem_u32x(const void* p) {
    return (unsigned)__cvta_generic_to_shared(const_cast<void*>(p));
}
__device__ __forceinline__ void ldsm_x4(unsigned* r, unsigned addr) {
    asm volatile("ldmatrix.sync.aligned.m8n8.x4.shared.b16 {%0,%1,%2,%3}, [%4];"
        : "=r"(r[0]), "=r"(r[1]), "=r"(r[2]), "=r"(r[3]) : "r"(addr));
}
__device__ __forceinline__ void mma16816(float* d, const unsigned* a, const unsigned* b) {
    asm volatile("mma.sync.aligned.m16n8k16.row.col.f32.bf16.bf16.f32 "
        "{%0,%1,%2,%3}, {%4,%5,%6,%7}, {%8,%9}, {%0,%1,%2,%3};"
        : "+f"(d[0]), "+f"(d[1]), "+f"(d[2]), "+f"(d[3])
        : "r"(a[0]), "r"(a[1]), "r"(a[2]), "r"(a[3]), "r"(b[0]), "r"(b[1]));
}

// load 64x32 fp32 tile (row stride ld) -> bf16 hi/lo SMEM tiles [64][40]
__device__ __forceinline__ void load_tile_conv(const float* __restrict__ src, int ld,
        __nv_bfloat16 (*H)[40], __nv_bfloat16 (*L)[40], int tid)
{
    #pragma unroll
    for (int it = 0; it < 2; it++) {
        int r = (tid >> 3) + it*32;
        int c = (tid & 7) * 4;
        float4 v = *reinterpret_cast<const float4*>(src + (long)r*ld + c);
        float vv[4] = {v.x, v.y, v.z, v.w};
        #pragma unroll
        for (int i = 0; i < 4; i++) {
            __nv_bfloat16 h = __float2bfloat16(vv[i]);
            H[r][c+i] = h;
            L[r][c+i] = __float2bfloat16(vv[i] - __bfloat162float(h));
        }
    }
}

// one K=32 chunk of 64x64 tile: acc += Ahi*Bhi + Ahi*Blo + Alo*Bhi
__device__ __forceinline__ void mma_k32(
    const __nv_bfloat16 (*Ah)[40], const __nv_bfloat16 (*Al)[40],
    const __nv_bfloat16 (*Bh)[40], const __nv_bfloat16 (*Bl)[40],
    float acc[4][4], int wr, int wc, int l)
{
    unsigned ah[2][4], al[2][4];
    int arow = wr*16 + (l & 15);
    int acol = (l >> 4) * 8;
    #pragma unroll
    for (int kh = 0; kh < 2; kh++) {
        ldsm_x4(ah[kh], smem_u32x(&Ah[arow][kh*16 + acol]));
        ldsm_x4(al[kh], smem_u32x(&Al[arow][kh*16 + acol]));
    }
    #pragma unroll
    for (int nb = 0; nb < 4; nb++) {
        unsigned bh[4], bl[4];
        int brow = wc*32 + nb*8 + (l & 7);
        int bcol = (l >> 3) * 8;
        ldsm_x4(bh, smem_u32x(&Bh[brow][bcol]));
        ldsm_x4(bl, smem_u32x(&Bl[brow][bcol]));
        #pragma unroll
        for (int kh = 0; kh < 2; kh++) {
            mma16816(acc[nb], ah[kh], bh + kh*2);
            mma16816(acc[nb], ah[kh], bl + kh*2);
            mma16816(acc[nb], al[kh], bh + kh*2);
        }
    }
}

// ---------------- P1: per-chunk means + normalized key means ----------------
__global__ void __launch_bounds__(384) p1_kernel(const float* __restrict__ x,
                                                 const float* __restrict__ gw) {
    extern __shared__ float Xs[];
    __shared__ float inv[CHn];
    __shared__ float red[12];
    int t = blockIdx.x, b = blockIdx.y, tid = threadIdx.x;
    int w = tid >> 5, l = tid & 31;
    const float* src = x + ((long)(b*Sn) + (long)t*CHn)*Dn;
    for (int i = tid; i < CHn*Dn; i += 384) Xs[i] = src[i];
    __syncthreads();
    for (int r = w; r < CHn; r += 12) {
        float s = 0.f;
        for (int d = l; d < Dn; d += 32) { float v = Xs[r*Dn+d]; s += v*v; }
        #pragma unroll
        for (int o = 16; o > 0; o >>= 1) s += __shfl_down_sync(0xffffffffu, s, o);
        if (l == 0) inv[r] = 1.0f / fmaxf(sqrtf(s), 1e-5f);
    }
    __syncthreads();
    float sx = 0.f, sk = 0.f;
    for (int c = 0; c < CHn; c++) {
        float v = Xs[c*Dn + tid];
        sx += v; sk += v * inv[c];
    }
    float km = sk * (1.0f/CHn);
    float wm = sx * (1.0f/CHn) - km;
    g_V[((long)b*256 + t)*Dn + tid]       = wm;
    g_V[((long)b*256 + 128 + t)*Dn + tid] = km;
    float gd = km * gw[tid];
    #pragma unroll
    for (int o = 16; o > 0; o >>= 1) gd += __shfl_down_sync(0xffffffffu, gd, o);
    if (l == 0) red[w] = gd;
    __syncthreads();
    if (tid == 0) {
        float s = 0.f;
        #pragma unroll
        for (int i = 0; i < 12; i++) s += red[i];
        g_gd[b*NCn + t] = s;
    }
}

// ---------------- SIMT 64x64 tile GEMM: C = A*B^T (fp32, feeds recurrence) ----------------
__device__ __forceinline__ void gemm_tile64(const float* __restrict__ A,
                                            const float* __restrict__ B,
                                            float* __restrict__ C,
                                            int K, int N) {
    __shared__ float As[64][33];
    __shared__ float Bs[32][65];
    int row0 = blockIdx.y * 64, col0 = blockIdx.x * 64;
    int tid = threadIdx.x, tx = tid & 15, ty = tid >> 4;
    int kk = tid & 31, rr = tid >> 5;
    float acc[4][4] = {};
    for (int k0 = 0; k0 < K; k0 += 32) {
        #pragma unroll
        for (int r = rr; r < 64; r += 8) As[r][kk] = A[(long)(row0 + r)*K + k0 + kk];
        #pragma unroll
        for (int c = rr; c < 64; c += 8) Bs[kk][c] = B[(long)(col0 + c)*K + k0 + kk];
        __syncthreads();
        #pragma unroll
        for (int k = 0; k < 32; k++) {
            float av[4], bv[4];
            #pragma unroll
            for (int i = 0; i < 4; i++) av[i] = As[ty*4+i][k];
            #pragma unroll
            for (int j = 0; j < 4; j++) bv[j] = Bs[k][tx*4+j];
            #pragma unroll
            for (int i = 0; i < 4; i++)
                #pragma unroll
                for (int j = 0; j < 4; j++)
                    acc[i][j] = fmaf(av[i], bv[j], acc[i][j]);
        }
        __syncthreads();
    }
    #pragma unroll
    for (int i = 0; i < 4; i++)
        #pragma unroll
        for (int j = 0; j < 4; j++)
            C[(long)(row0 + ty*4 + i)*N + col0 + tx*4 + j] = acc[i][j];
}

__global__ void __launch_bounds__(256) p2a_kernel(const float* __restrict__ M0) {
    int b = blockIdx.z;
    gemm_tile64(g_V + (long)b*256*Dn, M0, g_WW + (long)b*256*Dn, Dn, Dn);
}
__global__ void __launch_bounds__(256) p2b_kernel() {
    int b = blockIdx.z;
    gemm_tile64(g_V + (long)b*256*Dn, g_V + (long)b*256*Dn + 128*Dn,
                g_GG + (long)b*256*NCn, Dn, NCn);
}

// ---------------- P2c (tensor): P = X @ K^T, bf16 hi/lo split ----------------
__global__ void __launch_bounds__(256) p2c_mma(const float* __restrict__ x) {
    __shared__ __nv_bfloat16 Ah[64][40], Al[64][40], Bh[64][40], Bl[64][40];
    int b = blockIdx.z;
    int row0 = blockIdx.y * 64, col0 = blockIdx.x * 64;
    const float* A  = x   + (long)b*Sn*Dn + (long)row0*Dn;
    const float* Bm = g_V + (long)b*256*Dn + 128*Dn + (long)col0*Dn;
    int tid = threadIdx.x, l = tid & 31, w = tid >> 5;
    int wr = w & 3, wc = w >> 2;
    float acc[4][4] = {};
    for (int k0 = 0; k0 < Dn; k0 += 32) {
        load_tile_conv(A  + k0, Dn, Ah, Al, tid);
        load_tile_conv(Bm + k0, Dn, Bh, Bl, tid);
        __syncthreads();
        mma_k32(Ah, Al, Bh, Bl, acc, wr, wc, l);
        __syncthreads();
    }
    float* C = g_P + (long)b*Sn*NCn + (long)row0*NCn + col0;
    #pragma unroll
    for (int nb = 0; nb < 4; nb++) {
        int cc = wc*32 + nb*8 + (l & 3)*2;
        int rr = wr*16 + (l >> 2);
        C[(long)rr*NCn + cc]       = acc[nb][0];
        C[(long)rr*NCn + cc + 1]   = acc[nb][1];
        C[(long)(rr+8)*NCn + cc]   = acc[nb][2];
        C[(long)(rr+8)*NCn + cc+1] = acc[nb][3];
    }
}

// ---------------- P3: sequential recurrence, one CTA per batch ----------------
__global__ void __launch_bounds__(384) p3_kernel(const float* __restrict__ M0,
                                                 const float* __restrict__ gb,
                                                 const float* __restrict__ eta_raw,
                                                 const float* __restrict__ alpha_raw) {
    extern __shared__ float Es[];            // 128*384 floats = 192 KB
    __shared__ float2 cgh[NCn];
    __shared__ float rs[NCn];
    __shared__ float redA[12], redB[12];
    __shared__ float sQ;
    int b = blockIdx.x, tid = threadIdx.x;
    int w = tid >> 5, l = tid & 31;

    float eta   = 0.2f / (1.0f + expf(-eta_raw[0]));
    float alpha = 0.5f + 0.5f / (1.0f + expf(-alpha_raw[0]));
    float gbv   = gb[0];

    float s0 = 0.f;
    for (int i = tid; i < Dn*Dn; i += 384) { float v = M0[i]; s0 += v*v; }
    #pragma unroll
    for (int o = 16; o > 0; o >>= 1) s0 += __shfl_down_sync(0xffffffffu, s0, o);
    if (l == 0) redA[w] = s0;
    if (tid == 0) sQ = 1.0f;
    __syncthreads();
    float n2 = 0.f, Qr = 1.0f;
    if (tid == 0) { for (int i = 0; i < 12; i++) n2 += redA[i]; }

    const float* WWb = g_WW + (long)b*256*Dn;
    const float* GGb = g_GG + (long)b*256*NCn;

    for (int t = 0; t < NCn; t++) {
        if (tid < t) {
            float r = rs[tid];
            cgh[tid] = make_float2(r * GGb[t*NCn + tid], r * GGb[(128+t)*NCn + tid]);
        }
        __syncthreads();
        float acc_e = WWb[t*Dn + tid];
        float acc_m = WWb[(128+t)*Dn + tid];
        for (int j = 0; j < t; j++) {
            float e = Es[j*Dn + tid];
            float2 c = cgh[j];
            acc_e = fmaf(c.x, e, acc_e);
            acc_m = fmaf(c.y, e, acc_m);
        }
        float Q   = sQ;
        float err = Q * acc_e;
        float mk  = Q * acc_m;
        Es[t*Dn + tid] = err;
        g_E[((long)b*NCn + t)*Dn + tid] = err;
        float ee = err*err, em = err*mk;
        #pragma unroll
        for (int o = 16; o > 0; o >>= 1) {
            ee += __shfl_down_sync(0xffffffffu, ee, o);
            em += __shfl_down_sync(0xffffffffu, em, o);
        }
        if (l == 0) { redA[w] = ee; redB[w] = em; }
        __syncthreads();
        if (tid == 0) {
            float see = 0.f, sem = 0.f;
            #pragma unroll
            for (int i = 0; i < 12; i++) { see += redA[i]; sem += redB[i]; }
            float kk2  = GGb[(128+t)*NCn + t];
            float gate = 1.0f / (1.0f + expf(-(g_gd[b*NCn + t] + gbv)));
            float a  = gate*alpha + (1.0f - gate);
            float bb = gate*eta;
            float norm2 = a*a*n2 + 2.0f*a*bb*sem + bb*bb*see*kk2;
            float s = fminf(30.0f / (sqrtf(norm2) + 1e-6f), 1.0f);
            g_Qp[b*NCn + t] = Qr;
            float A = s*a, Bc = s*bb;
            float Qn = Qr*A;
            float rt = Bc / Qn;
            rs[t] = rt;
            g_r[b*NCn + t] = rt;
            n2 = s*s*norm2;
            Qr = Qn;
            sQ = Qn;
        }
        __syncthreads();
    }
    if (tid < NCn) g_dc[b*NCn + tid] = sQ * rs[tid];
    if (tid == 0)  g_QN[b] = sQ;
}

// ---------------- P4 (tensor): out = Q_{t-1}*(X@M0^T + P_masked @ diag(r) E) ----------------
__global__ void __launch_bounds__(256) p4_mma(const float* __restrict__ x,
                                              const float* __restrict__ M0,
                                              float* __restrict__ out) {
    __shared__ __nv_bfloat16 Ah[64][40], Al[64][40], Bh[64][40], Bl[64][40];
    __shared__ float rc[NCn];
    int ot = blockIdx.x, t = blockIdx.y, b = blockIdx.z;
    int col0 = ot * 64;
    int tid = threadIdx.x, l = tid & 31, w = tid >> 5;
    int wr = w & 3, wc = w >> 2;
    const float* Xc = x  + ((long)b*Sn + (long)t*CHn)*Dn;
    const float* Bm = M0 + (long)col0*Dn;
    float acc[4][4] = {};
    // phase 1: X @ M0^T (K = 384)
    for (int k0 = 0; k0 < Dn; k0 += 32) {
        load_tile_conv(Xc + k0, Dn, Ah, Al, tid);
        load_tile_conv(Bm + k0, Dn, Bh, Bl, tid);
        __syncthreads();
        mma_k32(Ah, Al, Bh, Bl, acc, wr, wc, l);
        __syncthreads();
    }
    // phase 2: P(:, j<t) @ diag(r) E  (K = t rounded up to 32)
    if (tid < NCn) rc[tid] = (tid < t) ? g_r[b*NCn + tid] : 0.0f;
    __syncthreads();
    const float* Pc = g_P + ((long)b*Sn + (long)t*CHn)*NCn;
    int Kt = (t + 31) & ~31;
    for (int k0 = 0; k0 < Kt; k0 += 32) {
        load_tile_conv(Pc + k0, NCn, Ah, Al, tid);
        {   // transpose-load B[n][k] = r_j * E[j][col0+n]
            // FIX (R6 bug): each thread now covers 8 n-values -> full 64 rows of Bh/Bl
            int kr = tid >> 3;            // k within chunk: 0..31
            int c8 = (tid & 7) * 8;       // n base: 0,8,...,56
            float rj = rc[k0 + kr];
            const float* Ep = g_E + ((long)b*NCn + k0 + kr)*Dn + col0 + c8;
            float4 v0 = *reinterpret_cast<const float4*>(Ep);
            float4 v1 = *reinterpret_cast<const float4*>(Ep + 4);
            float vv[8] = {v0.x*rj, v0.y*rj, v0.z*rj, v0.w*rj,
                           v1.x*rj, v1.y*rj, v1.z*rj, v1.w*rj};
            #pragma unroll
            for (int i = 0; i < 8; i++) {
                __nv_bfloat16 h = __float2bfloat16(vv[i]);
                Bh[c8+i][kr] = h;
                Bl[c8+i][kr] = __float2bfloat16(vv[i] - __bfloat162float(h));
            }
        }
        __syncthreads();
        mma_k32(Ah, Al, Bh, Bl, acc, wr, wc, l);
        __syncthreads();
    }
    float Qp = g_Qp[b*NCn + t];
    float* O = out + ((long)b*Sn + (long)t*CHn)*Dn + col0;
    #pragma unroll
    for (int nb = 0; nb < 4; nb++) {
        int cc = wc*32 + nb*8 + (l & 3)*2;
        int rr = wr*16 + (l >> 2);
        O[(long)rr*Dn + cc]       = Qp * acc[nb][0];
        O[(long)rr*Dn + cc + 1]   = Qp * acc[nb][1];
        O[(long)(rr+8)*Dn + cc]   = Qp * acc[nb][2];
        O[(long)(rr+8)*Dn + cc+1] = Qp * acc[nb][3];
    }
}

// ---------------- P5: M_fin = Q_N*M0 + E^T diag(Q_N r) K ----------------
__global__ void __launch_bounds__(256) p5_kernel(const float* __restrict__ M0,
                                                 float* __restrict__ out2) {
    __shared__ float As[32][65];
    __shared__ float Bs[32][65];
    int b = blockIdx.z;
    int row0 = blockIdx.y * 64, col0 = blockIdx.x * 64;
    int tid = threadIdx.x, tx = tid & 15, ty = tid >> 4;
    int kk = tid & 31, rr = tid >> 5;
    float acc[4][4] = {};
    for (int k0 = 0; k0 < NCn; k0 += 32) {
        for (int k = rr; k < 32; k += 8) {
            float dc = g_dc[b*NCn + k0 + k];
            #pragma unroll
            for (int c = kk; c < 64; c += 32) {
                As[k][c] = g_E[((long)b*NCn + k0 + k)*Dn + row0 + c] * dc;
                Bs[k][c] = g_V[((long)b*256 + 128 + k0 + k)*Dn + col0 + c];
            }
        }
        __syncthreads();
        #pragma unroll
        for (int k = 0; k < 32; k++) {
            float av[4], bv[4];
            #pragma unroll
            for (int i = 0; i < 4; i++) av[i] = As[k][ty*4+i];
            #pragma unroll
            for (int j = 0; j < 4; j++) bv[j] = Bs[k][tx*4+j];
            #pragma unroll
            for (int i = 0; i < 4; i++)
                #pragma unroll
                for (int j = 0; j < 4; j++)
                    acc[i][j] = fmaf(av[i], bv[j], acc[i][j]);
        }
        __syncthreads();
    }
    float qn = g_QN[b];
    #pragma unroll
    for (int i = 0; i < 4; i++)
        #pragma unroll
        for (int j = 0; j < 4; j++) {
            int o = row0 + ty*4 + i, d = col0 + tx*4 + j;
            out2[((long)b*Dn + o)*Dn + d] = qn * M0[(long)o*Dn + d] + acc[i][j];
        }
}

extern "C" void kernel_launch(void* const* d_in, const int* in_sizes, int n_in,
                              void* d_out, int out_size) {
    const float* x         = (const float*)d_in[0];
    const float* M0        = (const float*)d_in[1];
    const float* eta_raw   = (const float*)d_in[2];
    const float* alpha_raw = (const float*)d_in[3];
    const float* gw        = (const float*)d_in[4];
    const float* gb        = (const float*)d_in[5];
    float* out = (float*)d_out;

    cudaFuncSetAttribute(p1_kernel, cudaFuncAttributeMaxDynamicSharedMemorySize, CHn*Dn*4);
    cudaFuncSetAttribute(p3_kernel, cudaFuncAttributeMaxDynamicSharedMemorySize, NCn*Dn*4);

    p1_kernel<<<dim3(NCn, Bn), 384, CHn*Dn*4>>>(x, gw);
    p2a_kernel<<<dim3(Dn/64, 256/64, Bn), 256>>>(M0);
    p2b_kernel<<<dim3(NCn/64, 256/64, Bn), 256>>>();
    p2c_mma<<<dim3(NCn/64, Sn/64, Bn), 256>>>(x);
    p3_kernel<<<Bn, 384, NCn*Dn*4>>>(M0, gb, eta_raw, alpha_raw);
    p4_mma<<<dim3(Dn/64, NCn, Bn), 256>>>(x, M0, out);
    if (out_size >= OUT_ELEMS + MFIN_ELEMS)
        p5_kernel<<<dim3(Dn/64, Dn/64, Bn), 256>>>(M0, out + OUT_ELEMS);
}